// round 1
// baseline (speedup 1.0000x reference)
#include <cuda_runtime.h>
#include <mma.h>
#include <math.h>

using namespace nvcuda;

// Problem shape (fixed for this dataset instance)
constexpr int Bb = 4;
constexpr int Tt = 4096;
constexpr int Dd = 2048;
constexpr int BT = Bb * Tt;           // 16384 rows
constexpr float EPS = 1e-5f;

// Scratch (device globals — no allocation allowed)
__device__ float g_iraw[(size_t)BT * Dd];
__device__ float g_fraw[(size_t)BT * Dd];
__device__ float g_gg  [(size_t)BT * Dd];
__device__ float g_o   [(size_t)BT * Dd];
__device__ float g_u   [(size_t)BT * Dd];

// ---------------------------------------------------------------------------
// TF32 wmma GEMM: C[M,N] = A[M,K] * B[K,N], all row-major fp32.
// Block tile 128x128, K-tile 32. 8 warps: 2(m) x 4(n), each warp 64x32
// via 4x2 fragments of 16x16x8.
// ---------------------------------------------------------------------------
#define BM 128
#define BN 128
#define BK 32

__global__ __launch_bounds__(256, 2)
void gemm_tf32(const float* __restrict__ A, const float* __restrict__ Bm,
               float* __restrict__ C, int M, int N, int K)
{
    __shared__ float sA[BM][BK + 4];
    __shared__ float sB[BK][BN + 4];

    const int tid  = threadIdx.x;
    const int warp = tid >> 5;
    const int wm   = warp >> 2;   // 0..1
    const int wn   = warp & 3;    // 0..3
    const int m0   = blockIdx.y * BM;
    const int n0   = blockIdx.x * BN;

    wmma::fragment<wmma::accumulator, 16, 16, 8, float> acc[4][2];
#pragma unroll
    for (int i = 0; i < 4; i++)
#pragma unroll
        for (int j = 0; j < 2; j++)
            wmma::fill_fragment(acc[i][j], 0.0f);

    for (int k0 = 0; k0 < K; k0 += BK) {
        // Load A tile: 128x32 = 1024 float4, 4 per thread
#pragma unroll
        for (int i = 0; i < 4; i++) {
            int e  = tid + i * 256;
            int r  = e >> 3;        // 8 float4 per row
            int c4 = e & 7;
            float4 v = *reinterpret_cast<const float4*>(
                &A[(size_t)(m0 + r) * K + k0 + c4 * 4]);
            *reinterpret_cast<float4*>(&sA[r][c4 * 4]) = v;
        }
        // Load B tile: 32x128 = 1024 float4, 4 per thread
#pragma unroll
        for (int i = 0; i < 4; i++) {
            int e  = tid + i * 256;
            int r  = e >> 5;        // 32 float4 per row
            int c4 = e & 31;
            float4 v = *reinterpret_cast<const float4*>(
                &Bm[(size_t)(k0 + r) * N + n0 + c4 * 4]);
            *reinterpret_cast<float4*>(&sB[r][c4 * 4]) = v;
        }
        __syncthreads();

#pragma unroll
        for (int kk = 0; kk < BK; kk += 8) {
            wmma::fragment<wmma::matrix_a, 16, 16, 8, wmma::precision::tf32,
                           wmma::row_major> af[4];
            wmma::fragment<wmma::matrix_b, 16, 16, 8, wmma::precision::tf32,
                           wmma::row_major> bf[2];
#pragma unroll
            for (int im = 0; im < 4; im++) {
                wmma::load_matrix_sync(af[im], &sA[wm * 64 + im * 16][kk], BK + 4);
#pragma unroll
                for (int t = 0; t < af[im].num_elements; t++)
                    af[im].x[t] = wmma::__float_to_tf32(af[im].x[t]);
            }
#pragma unroll
            for (int in = 0; in < 2; in++) {
                wmma::load_matrix_sync(bf[in], &sB[kk][wn * 32 + in * 16], BN + 4);
#pragma unroll
                for (int t = 0; t < bf[in].num_elements; t++)
                    bf[in].x[t] = wmma::__float_to_tf32(bf[in].x[t]);
            }
#pragma unroll
            for (int im = 0; im < 4; im++)
#pragma unroll
                for (int in = 0; in < 2; in++)
                    wmma::mma_sync(acc[im][in], af[im], bf[in], acc[im][in]);
        }
        __syncthreads();
    }

#pragma unroll
    for (int im = 0; im < 4; im++)
#pragma unroll
        for (int in = 0; in < 2; in++)
            wmma::store_matrix_sync(
                &C[(size_t)(m0 + wm * 64 + im * 16) * N + n0 + wn * 32 + in * 16],
                acc[im][in], N, wmma::mem_row_major);
}

// ---------------------------------------------------------------------------
// Linear recurrence: h_t = sigmoid(f_t) * h_{t-1} + silu(i_t) * sigmoid(-f_t)
// One thread per (b, d) channel; warp-coalesced along d.
// ---------------------------------------------------------------------------
__global__ void scan_kernel(const float* __restrict__ iraw,
                            const float* __restrict__ fraw,
                            float* __restrict__ o)
{
    int c = blockIdx.x * blockDim.x + threadIdx.x;   // 0 .. B*D-1
    int b = c / Dd;
    int d = c - b * Dd;
    size_t base = (size_t)b * Tt * Dd + d;

    float h = 0.0f;
#pragma unroll 4
    for (int t = 0; t < Tt; t++) {
        size_t idx = base + (size_t)t * Dd;
        float fr = fraw[idx];
        float ir = iraw[idx];
        float a    = 1.0f / (1.0f + expf(-fr));          // sigmoid(f)
        float gate = 1.0f / (1.0f + expf( fr));          // sigmoid(-f)
        float inp  = (ir / (1.0f + expf(-ir))) * gate;   // silu(i)*sigmoid(-f)
        h = fmaf(a, h, inp);
        o[idx] = h;
    }
}

// ---------------------------------------------------------------------------
// u = RMSNorm(o) * w * (g * sigmoid(g)) per (b,t) row
// ---------------------------------------------------------------------------
__global__ void norm_gate_kernel(const float* __restrict__ o,
                                 const float* __restrict__ g,
                                 const float* __restrict__ w,
                                 float* __restrict__ u)
{
    int row = blockIdx.x;
    const float* op = o + (size_t)row * Dd;
    const float* gp = g + (size_t)row * Dd;
    float*       up = u + (size_t)row * Dd;

    float s = 0.0f;
    for (int j = threadIdx.x; j < Dd; j += blockDim.x) {
        float v = op[j];
        s = fmaf(v, v, s);
    }
    __shared__ float red[256];
    red[threadIdx.x] = s;
    __syncthreads();
#pragma unroll
    for (int k = 128; k > 0; k >>= 1) {
        if (threadIdx.x < k) red[threadIdx.x] += red[threadIdx.x + k];
        __syncthreads();
    }
    float r = rsqrtf(red[0] * (1.0f / Dd) + EPS);

    for (int j = threadIdx.x; j < Dd; j += blockDim.x) {
        float gv = gp[j];
        float sw = gv / (1.0f + expf(-gv));   // g * sigmoid(g)
        up[j] = op[j] * r * w[j] * sw;
    }
}

// ---------------------------------------------------------------------------
extern "C" void kernel_launch(void* const* d_in, const int* in_sizes, int n_in,
                              void* d_out, int out_size)
{
    const float* x  = (const float*)d_in[0];
    const float* Wi = (const float*)d_in[1];
    const float* Wf = (const float*)d_in[2];
    const float* Wg = (const float*)d_in[3];
    const float* Wo = (const float*)d_in[4];
    const float* gw = (const float*)d_in[5];
    float* out = (float*)d_out;

    float *iraw, *fraw, *gg, *o, *u;
    cudaGetSymbolAddress((void**)&iraw, g_iraw);
    cudaGetSymbolAddress((void**)&fraw, g_fraw);
    cudaGetSymbolAddress((void**)&gg,   g_gg);
    cudaGetSymbolAddress((void**)&o,    g_o);
    cudaGetSymbolAddress((void**)&u,    g_u);

    dim3 ggrid(Dd / BN, BT / BM);   // (16, 128)
    dim3 gblk(256);

    gemm_tf32<<<ggrid, gblk>>>(x, Wi, iraw, BT, Dd, Dd);
    gemm_tf32<<<ggrid, gblk>>>(x, Wf, fraw, BT, Dd, Dd);
    gemm_tf32<<<ggrid, gblk>>>(x, Wg, gg,   BT, Dd, Dd);

    scan_kernel<<<(Bb * Dd) / 256, 256>>>(iraw, fraw, o);

    norm_gate_kernel<<<BT, 256>>>(o, gg, gw, u);

    gemm_tf32<<<ggrid, gblk>>>(u, Wo, out, BT, Dd, Dd);
}

// round 2
// speedup vs baseline: 1.2582x; 1.2582x over previous
#include <cuda_runtime.h>
#include <mma.h>
#include <math.h>
#include <stdint.h>

using namespace nvcuda;

// Problem shape (fixed for this dataset instance)
constexpr int Bb = 4;
constexpr int Tt = 4096;
constexpr int Dd = 2048;
constexpr int BT = Bb * Tt;           // 16384 rows
constexpr float EPS = 1e-5f;

// Scan chunking
constexpr int NC = 32;                // chunks along T
constexpr int CH = Tt / NC;           // 128 steps per chunk

// Scratch (device globals — no allocation allowed)
__device__ float g_iraw[(size_t)BT * Dd];
__device__ float g_fraw[(size_t)BT * Dd];
__device__ float g_gg  [(size_t)BT * Dd];
__device__ float g_o   [(size_t)BT * Dd];
__device__ float g_u   [(size_t)BT * Dd];
__device__ float g_xr  [(size_t)BT * Dd];      // tf32-rounded x
__device__ float g_wr  [(size_t)4 * Dd * Dd];  // tf32-rounded Wi,Wf,Wg,Wo
__device__ float g_cA  [(size_t)Bb * NC * Dd]; // chunk carry: prod(a)
__device__ float g_cH  [(size_t)Bb * NC * Dd]; // chunk carry: h_end
__device__ float g_cIn [(size_t)Bb * NC * Dd]; // exclusive carry into chunk

// ---------------------------------------------------------------------------
__device__ __forceinline__ float tf32r(float x) {
    uint32_t u;
    asm("cvt.rna.tf32.f32 %0, %1;" : "=r"(u) : "f"(x));
    return __uint_as_float(u);
}

__global__ void round_tf32_kernel(const float* __restrict__ in,
                                  float* __restrict__ out, int n4)
{
    int i = blockIdx.x * blockDim.x + threadIdx.x;
    if (i < n4) {
        float4 v = reinterpret_cast<const float4*>(in)[i];
        v.x = tf32r(v.x); v.y = tf32r(v.y); v.z = tf32r(v.z); v.w = tf32r(v.w);
        reinterpret_cast<float4*>(out)[i] = v;
    }
}

// ---------------------------------------------------------------------------
// TF32 wmma GEMM, cp.async double-buffered. C[M,N] = A[M,K]*B[K,N] row-major.
// Inputs are already tf32-rounded -> no in-loop conversion.
// Block tile 128x128, K-tile 32, 256 threads (8 warps: 2m x 4n, warp 64x32).
// ---------------------------------------------------------------------------
#define BM 128
#define BN 128
#define BK 32
constexpr int ASZ = BM * (BK + 4);    // 128*36 floats
constexpr int BSZ = BK * (BN + 4);    // 32*132 floats
constexpr int STG = ASZ + BSZ;
constexpr int GEMM_SMEM = 2 * STG * 4;  // bytes (70656)

__global__ __launch_bounds__(256)
void gemm_tf32(const float* __restrict__ A, const float* __restrict__ Bm,
               float* __restrict__ C, int M, int N, int K)
{
    extern __shared__ float smem[];

    const int tid  = threadIdx.x;
    const int warp = tid >> 5;
    const int wm   = warp >> 2;   // 0..1
    const int wn   = warp & 3;    // 0..3
    const int m0   = blockIdx.y * BM;
    const int n0   = blockIdx.x * BN;

    auto issue = [&](int kt, int buf) {
        float* sA = smem + buf * STG;
        float* sB = sA + ASZ;
        const int k0 = kt * BK;
#pragma unroll
        for (int i = 0; i < 4; i++) {
            int e = tid + i * 256;
            int r = e >> 3, c4 = e & 7;
            uint32_t dst = (uint32_t)__cvta_generic_to_shared(&sA[r * (BK + 4) + c4 * 4]);
            const float* src = &A[(size_t)(m0 + r) * K + k0 + c4 * 4];
            asm volatile("cp.async.cg.shared.global [%0], [%1], 16;\n"
                         :: "r"(dst), "l"(src));
        }
#pragma unroll
        for (int i = 0; i < 4; i++) {
            int e = tid + i * 256;
            int r = e >> 5, c4 = e & 31;
            uint32_t dst = (uint32_t)__cvta_generic_to_shared(&sB[r * (BN + 4) + c4 * 4]);
            const float* src = &Bm[(size_t)(k0 + r) * N + n0 + c4 * 4];
            asm volatile("cp.async.cg.shared.global [%0], [%1], 16;\n"
                         :: "r"(dst), "l"(src));
        }
        asm volatile("cp.async.commit_group;\n");
    };

    wmma::fragment<wmma::accumulator, 16, 16, 8, float> acc[4][2];
#pragma unroll
    for (int i = 0; i < 4; i++)
#pragma unroll
        for (int j = 0; j < 2; j++)
            wmma::fill_fragment(acc[i][j], 0.0f);

    issue(0, 0);

    const int KT = K / BK;
    for (int kt = 0; kt < KT; kt++) {
        if (kt + 1 < KT) {
            issue(kt + 1, (kt + 1) & 1);
            asm volatile("cp.async.wait_group 1;\n");
        } else {
            asm volatile("cp.async.wait_group 0;\n");
        }
        __syncthreads();

        float* sA = smem + (kt & 1) * STG;
        float* sB = sA + ASZ;

#pragma unroll
        for (int kk = 0; kk < BK; kk += 8) {
            wmma::fragment<wmma::matrix_a, 16, 16, 8, wmma::precision::tf32,
                           wmma::row_major> af[4];
            wmma::fragment<wmma::matrix_b, 16, 16, 8, wmma::precision::tf32,
                           wmma::row_major> bf[2];
#pragma unroll
            for (int im = 0; im < 4; im++)
                wmma::load_matrix_sync(af[im], &sA[(wm * 64 + im * 16) * (BK + 4) + kk],
                                       BK + 4);
#pragma unroll
            for (int in = 0; in < 2; in++)
                wmma::load_matrix_sync(bf[in], &sB[kk * (BN + 4) + wn * 32 + in * 16],
                                       BN + 4);
#pragma unroll
            for (int im = 0; im < 4; im++)
#pragma unroll
                for (int in = 0; in < 2; in++)
                    wmma::mma_sync(acc[im][in], af[im], bf[in], acc[im][in]);
        }
        __syncthreads();
    }

#pragma unroll
    for (int im = 0; im < 4; im++)
#pragma unroll
        for (int in = 0; in < 2; in++)
            wmma::store_matrix_sync(
                &C[(size_t)(m0 + wm * 64 + im * 16) * N + n0 + wn * 32 + in * 16],
                acc[im][in], N, wmma::mem_row_major);
}

// ---------------------------------------------------------------------------
// Parallel scan, 3 passes. h_t = sigmoid(f)*h + silu(i)*sigmoid(-f)
// ---------------------------------------------------------------------------
// Pass 1: local scan within each chunk; emit per-chunk (prodA, hEnd).
__global__ void scan_pass1(const float* __restrict__ iraw,
                           const float* __restrict__ fraw,
                           float* __restrict__ o,
                           float* __restrict__ cA,
                           float* __restrict__ cH)
{
    const int blocksPerBC = Dd / 256;                // 8
    int d  = (blockIdx.x % blocksPerBC) * 256 + threadIdx.x;
    int bc = blockIdx.x / blocksPerBC;               // b*NC + c
    int b  = bc / NC;
    int c  = bc % NC;
    size_t base = ((size_t)b * Tt + (size_t)c * CH) * Dd + d;

    float h = 0.0f, pa = 1.0f;
#pragma unroll 4
    for (int t = 0; t < CH; t++) {
        size_t idx = base + (size_t)t * Dd;
        float fr = fraw[idx];
        float ir = iraw[idx];
        float a    = 1.0f / (1.0f + expf(-fr));
        float gate = 1.0f / (1.0f + expf( fr));
        float inp  = (ir / (1.0f + expf(-ir))) * gate;
        h  = fmaf(a, h, inp);
        pa *= a;
        o[idx] = h;
    }
    cA[(size_t)bc * Dd + d] = pa;
    cH[(size_t)bc * Dd + d] = h;
}

// Pass 2: sequential scan over NC chunk carries per channel (tiny).
__global__ void scan_pass2(const float* __restrict__ cA,
                           const float* __restrict__ cH,
                           float* __restrict__ cIn)
{
    int ch = blockIdx.x * blockDim.x + threadIdx.x;  // 0..B*D-1
    int b  = ch / Dd;
    int d  = ch - b * Dd;
    float H = 0.0f;
#pragma unroll
    for (int c = 0; c < NC; c++) {
        size_t idx = ((size_t)b * NC + c) * Dd + d;
        cIn[idx] = H;
        H = fmaf(cA[idx], H, cH[idx]);
    }
}

// Pass 3: fixup: o[t] += carryIn * cumprod(a) within chunk (skip chunk 0).
__global__ void scan_pass3(const float* __restrict__ fraw,
                           const float* __restrict__ cIn,
                           float* __restrict__ o)
{
    const int blocksPerBC = Dd / 256;
    int d  = (blockIdx.x % blocksPerBC) * 256 + threadIdx.x;
    int bc = blockIdx.x / blocksPerBC;
    int b  = bc / NC;
    int c  = bc % NC;
    if (c == 0) return;

    float cin = cIn[(size_t)bc * Dd + d];
    size_t base = ((size_t)b * Tt + (size_t)c * CH) * Dd + d;
    float pa = cin;
#pragma unroll 4
    for (int t = 0; t < CH; t++) {
        size_t idx = base + (size_t)t * Dd;
        float fr = fraw[idx];
        float a  = 1.0f / (1.0f + expf(-fr));
        pa *= a;
        o[idx] += pa;
    }
}

// ---------------------------------------------------------------------------
// u = tf32_round( RMSNorm(o) * w * (g * sigmoid(g)) ) per (b,t) row
// ---------------------------------------------------------------------------
__global__ __launch_bounds__(256)
void norm_gate_kernel(const float* __restrict__ o,
                      const float* __restrict__ g,
                      const float* __restrict__ w,
                      float* __restrict__ u)
{
    int row = blockIdx.x;
    const float4* op = reinterpret_cast<const float4*>(o + (size_t)row * Dd);
    const float4* gp = reinterpret_cast<const float4*>(g + (size_t)row * Dd);
    const float4* wp = reinterpret_cast<const float4*>(w);
    float4*       up = reinterpret_cast<float4*>(u + (size_t)row * Dd);

    float4 va[2];
    float s = 0.0f;
#pragma unroll
    for (int i = 0; i < 2; i++) {
        va[i] = op[threadIdx.x + i * 256];
        s += va[i].x * va[i].x + va[i].y * va[i].y
           + va[i].z * va[i].z + va[i].w * va[i].w;
    }
    // warp + block reduce
#pragma unroll
    for (int k = 16; k > 0; k >>= 1)
        s += __shfl_xor_sync(0xffffffffu, s, k);
    __shared__ float red[8];
    if ((threadIdx.x & 31) == 0) red[threadIdx.x >> 5] = s;
    __syncthreads();
    if (threadIdx.x < 8) {
        float v = red[threadIdx.x];
#pragma unroll
        for (int k = 4; k > 0; k >>= 1)
            v += __shfl_xor_sync(0xffu, v, k);
        if (threadIdx.x == 0) red[0] = v;
    }
    __syncthreads();
    float r = rsqrtf(red[0] * (1.0f / Dd) + EPS);

#pragma unroll
    for (int i = 0; i < 2; i++) {
        float4 vg = gp[threadIdx.x + i * 256];
        float4 vw = wp[threadIdx.x + i * 256];
        float4 out;
        out.x = tf32r(va[i].x * r * vw.x * (vg.x / (1.0f + expf(-vg.x))));
        out.y = tf32r(va[i].y * r * vw.y * (vg.y / (1.0f + expf(-vg.y))));
        out.z = tf32r(va[i].z * r * vw.z * (vg.z / (1.0f + expf(-vg.z))));
        out.w = tf32r(va[i].w * r * vw.w * (vg.w / (1.0f + expf(-vg.w))));
        up[threadIdx.x + i * 256] = out;
    }
}

// ---------------------------------------------------------------------------
extern "C" void kernel_launch(void* const* d_in, const int* in_sizes, int n_in,
                              void* d_out, int out_size)
{
    const float* x  = (const float*)d_in[0];
    const float* Wi = (const float*)d_in[1];
    const float* Wf = (const float*)d_in[2];
    const float* Wg = (const float*)d_in[3];
    const float* Wo = (const float*)d_in[4];
    const float* gw = (const float*)d_in[5];
    float* out = (float*)d_out;

    float *iraw, *fraw, *gg, *o, *u, *xr, *wr, *cA, *cH, *cIn;
    cudaGetSymbolAddress((void**)&iraw, g_iraw);
    cudaGetSymbolAddress((void**)&fraw, g_fraw);
    cudaGetSymbolAddress((void**)&gg,   g_gg);
    cudaGetSymbolAddress((void**)&o,    g_o);
    cudaGetSymbolAddress((void**)&u,    g_u);
    cudaGetSymbolAddress((void**)&xr,   g_xr);
    cudaGetSymbolAddress((void**)&wr,   g_wr);
    cudaGetSymbolAddress((void**)&cA,   g_cA);
    cudaGetSymbolAddress((void**)&cH,   g_cH);
    cudaGetSymbolAddress((void**)&cIn,  g_cIn);

    cudaFuncSetAttribute(gemm_tf32,
                         cudaFuncAttributeMaxDynamicSharedMemorySize, GEMM_SMEM);

    const size_t WSZ = (size_t)Dd * Dd;

    // Pre-round inputs to tf32 (removes all in-loop conversion from GEMMs)
    {
        int n4x = (int)((size_t)BT * Dd / 4);
        int n4w = (int)(WSZ / 4);
        round_tf32_kernel<<<n4x / 256, 256>>>(x,  xr, n4x);
        round_tf32_kernel<<<n4w / 256, 256>>>(Wi, wr + 0 * WSZ, n4w);
        round_tf32_kernel<<<n4w / 256, 256>>>(Wf, wr + 1 * WSZ, n4w);
        round_tf32_kernel<<<n4w / 256, 256>>>(Wg, wr + 2 * WSZ, n4w);
        round_tf32_kernel<<<n4w / 256, 256>>>(Wo, wr + 3 * WSZ, n4w);
    }

    dim3 ggrid(Dd / BN, BT / BM);   // (16, 128)
    dim3 gblk(256);

    gemm_tf32<<<ggrid, gblk, GEMM_SMEM>>>(xr, wr + 0 * WSZ, iraw, BT, Dd, Dd);
    gemm_tf32<<<ggrid, gblk, GEMM_SMEM>>>(xr, wr + 1 * WSZ, fraw, BT, Dd, Dd);
    gemm_tf32<<<ggrid, gblk, GEMM_SMEM>>>(xr, wr + 2 * WSZ, gg,   BT, Dd, Dd);

    const int scanBlocks = Bb * NC * (Dd / 256);   // 1024
    scan_pass1<<<scanBlocks, 256>>>(iraw, fraw, o, cA, cH);
    scan_pass2<<<(Bb * Dd) / 256, 256>>>(cA, cH, cIn);
    scan_pass3<<<scanBlocks, 256>>>(fraw, cIn, o);

    norm_gate_kernel<<<BT, 256>>>(o, gg, gw, u);

    gemm_tf32<<<ggrid, gblk, GEMM_SMEM>>>(u, wr + 3 * WSZ, out, BT, Dd, Dd);
}

// round 4
// speedup vs baseline: 3.1524x; 2.5055x over previous
#include <cuda_runtime.h>
#include <math.h>
#include <stdint.h>

// Problem shape (fixed for this dataset instance)
constexpr int Bb = 4;
constexpr int Tt = 4096;
constexpr int Dd = 2048;
constexpr int BT = Bb * Tt;           // 16384 rows
constexpr float EPS = 1e-5f;

// Scan chunking
constexpr int NC = 32;
constexpr int CH = Tt / NC;           // 128

// GEMM tiling (mma.sync tf32)
constexpr int BM = 128;
constexpr int BN = 128;
constexpr int BK = 16;
constexpr int LDA_S = 20;             // padded floats per A row (bank-clean)
constexpr int LDB_S = 136;            // padded floats per B row (bank-clean)
constexpr int STAGES = 4;
constexpr int A_FLOATS = BM * LDA_S;  // 2560
constexpr int B_FLOATS = BK * LDB_S;  // 2176
constexpr int STG_FLOATS = A_FLOATS + B_FLOATS;       // 4736
constexpr int GEMM_SMEM = STAGES * STG_FLOATS * 4;    // 75776 bytes

// Scratch (device globals — no allocation allowed)
__device__ float g_iraw[(size_t)BT * Dd];
__device__ float g_fraw[(size_t)BT * Dd];
__device__ float g_gg  [(size_t)BT * Dd];
__device__ float g_o   [(size_t)BT * Dd];
__device__ float g_u   [(size_t)BT * Dd];
__device__ float g_xr  [(size_t)BT * Dd];      // tf32-rounded x
__device__ float g_wr  [(size_t)4 * Dd * Dd];  // tf32-rounded weights (native [K][N])
__device__ float g_cA  [(size_t)Bb * NC * Dd];
__device__ float g_cH  [(size_t)Bb * NC * Dd];
__device__ float g_cIn [(size_t)Bb * NC * Dd];

// ---------------------------------------------------------------------------
__device__ __forceinline__ float tf32r(float x) {
    uint32_t u;
    asm("cvt.rna.tf32.f32 %0, %1;" : "=r"(u) : "f"(x));
    return __uint_as_float(u);
}

__device__ __forceinline__ void cp16(uint32_t dst, const void* src) {
    asm volatile("cp.async.cg.shared.global [%0], [%1], 16;\n" :: "r"(dst), "l"(src));
}

__device__ __forceinline__ void mma1688(float* d, const uint32_t* a, const uint32_t* b) {
    asm volatile(
        "mma.sync.aligned.m16n8k8.row.col.f32.tf32.tf32.f32 "
        "{%0,%1,%2,%3}, {%4,%5,%6,%7}, {%8,%9}, {%0,%1,%2,%3};"
        : "+f"(d[0]), "+f"(d[1]), "+f"(d[2]), "+f"(d[3])
        : "r"(a[0]), "r"(a[1]), "r"(a[2]), "r"(a[3]), "r"(b[0]), "r"(b[1]));
}

// ---------------------------------------------------------------------------
__global__ void round_tf32_kernel(const float* __restrict__ in,
                                  float* __restrict__ out, int n4)
{
    int i = blockIdx.x * blockDim.x + threadIdx.x;
    if (i < n4) {
        float4 v = reinterpret_cast<const float4*>(in)[i];
        v.x = tf32r(v.x); v.y = tf32r(v.y); v.z = tf32r(v.z); v.w = tf32r(v.w);
        reinterpret_cast<float4*>(out)[i] = v;
    }
}

// ---------------------------------------------------------------------------
// C[M,N] = A[M,K] * B[K,N]; A row-major K-contig, B row-major N-contig.
// Both pre-rounded to tf32. mma.sync m16n8k8, 4-stage cp.async.
// ---------------------------------------------------------------------------
__global__ __launch_bounds__(256, 2)
void gemm_mma(const float* __restrict__ A, const float* __restrict__ Bw,
              float* __restrict__ C, int M, int N, int K)
{
    extern __shared__ float smem[];

    const int tid  = threadIdx.x;
    const int warp = tid >> 5;
    const int lane = tid & 31;
    const int wm   = warp >> 2;          // 0..1
    const int wn   = warp & 3;           // 0..3
    const int gid  = lane >> 2;          // groupID 0..7
    const int tig  = lane & 3;           // thread-in-group
    const int m0   = blockIdx.y * BM;
    const int n0   = blockIdx.x * BN;

    float acc[4][4][4];                  // [im][in][reg]
#pragma unroll
    for (int i = 0; i < 4; i++)
#pragma unroll
        for (int j = 0; j < 4; j++)
#pragma unroll
            for (int r = 0; r < 4; r++)
                acc[i][j][r] = 0.0f;

    const uint32_t smem_b = (uint32_t)__cvta_generic_to_shared(smem);

    auto load_stage = [&](int kt, int s) {
        const int k0 = kt * BK;
        const uint32_t sa = smem_b + s * STG_FLOATS * 4;
        const uint32_t sb = sa + A_FLOATS * 4;
        // A: 128 rows x 4 float4
#pragma unroll
        for (int i = 0; i < 2; i++) {
            int e = tid + i * 256;
            int r = e >> 2, c4 = e & 3;
            cp16(sa + (r * LDA_S + c4 * 4) * 4,
                 A + (size_t)(m0 + r) * K + k0 + c4 * 4);
        }
        // B: 16 rows x 32 float4
#pragma unroll
        for (int i = 0; i < 2; i++) {
            int e = tid + i * 256;
            int r = e >> 5, c4 = e & 31;
            cp16(sb + (r * LDB_S + c4 * 4) * 4,
                 Bw + (size_t)(k0 + r) * N + n0 + c4 * 4);
        }
        asm volatile("cp.async.commit_group;\n" ::: "memory");
    };

    const int KT = K / BK;               // 128
    load_stage(0, 0);
    load_stage(1, 1);
    load_stage(2, 2);

    for (int kt = 0; kt < KT; kt++) {
        const int s = kt & 3;
        if (kt < KT - 2)
            asm volatile("cp.async.wait_group 2;\n" ::: "memory");
        else if (kt == KT - 2)
            asm volatile("cp.async.wait_group 1;\n" ::: "memory");
        else
            asm volatile("cp.async.wait_group 0;\n" ::: "memory");
        __syncthreads();

        const float* sA = smem + s * STG_FLOATS;
        const float* sB = sA + A_FLOATS;

#pragma unroll
        for (int kk = 0; kk < 2; kk++) {             // two k8 steps
            uint32_t af[4][4];
            uint32_t bf[4][2];
#pragma unroll
            for (int im = 0; im < 4; im++) {
                int r0 = wm * 64 + im * 16 + gid;
                int c0 = kk * 8 + tig;
                af[im][0] = __float_as_uint(sA[r0 * LDA_S + c0]);
                af[im][1] = __float_as_uint(sA[(r0 + 8) * LDA_S + c0]);
                af[im][2] = __float_as_uint(sA[r0 * LDA_S + c0 + 4]);
                af[im][3] = __float_as_uint(sA[(r0 + 8) * LDA_S + c0 + 4]);
            }
#pragma unroll
            for (int in = 0; in < 4; in++) {
                int n = wn * 32 + in * 8 + gid;
                int k = kk * 8 + tig;
                bf[in][0] = __float_as_uint(sB[k * LDB_S + n]);
                bf[in][1] = __float_as_uint(sB[(k + 4) * LDB_S + n]);
            }
#pragma unroll
            for (int im = 0; im < 4; im++)
#pragma unroll
                for (int in = 0; in < 4; in++)
                    mma1688(acc[im][in], af[im], bf[in]);
        }

        // Issue next load AFTER compute: overwrites buffer (kt-1)&3, which all
        // warps finished before this iteration's __syncthreads.
        if (kt + 3 < KT)
            load_stage(kt + 3, (kt + 3) & 3);
    }

    // Epilogue: direct stores (float2 per fragment half)
#pragma unroll
    for (int im = 0; im < 4; im++) {
        int row0 = m0 + wm * 64 + im * 16 + gid;
#pragma unroll
        for (int in = 0; in < 4; in++) {
            int col = n0 + wn * 32 + in * 8 + 2 * tig;
            float2 v0 = make_float2(acc[im][in][0], acc[im][in][1]);
            float2 v1 = make_float2(acc[im][in][2], acc[im][in][3]);
            *reinterpret_cast<float2*>(&C[(size_t)row0 * N + col])       = v0;
            *reinterpret_cast<float2*>(&C[(size_t)(row0 + 8) * N + col]) = v1;
        }
    }
}

// ---------------------------------------------------------------------------
// Parallel scan (3 passes). h_t = a*h + silu(i)*(1-a), a = sigmoid(f)
// ---------------------------------------------------------------------------
__global__ void scan_pass1(const float* __restrict__ iraw,
                           const float* __restrict__ fraw,
                           float* __restrict__ o,
                           float* __restrict__ cA,
                           float* __restrict__ cH)
{
    const int blocksPerBC = Dd / 256;            // 8
    int d  = (blockIdx.x % blocksPerBC) * 256 + threadIdx.x;
    int bc = blockIdx.x / blocksPerBC;
    int b  = bc / NC;
    int c  = bc % NC;
    size_t base = ((size_t)b * Tt + (size_t)c * CH) * Dd + d;

    float h = 0.0f, pa = 1.0f;
#pragma unroll 4
    for (int t = 0; t < CH; t++) {
        size_t idx = base + (size_t)t * Dd;
        float fr = fraw[idx];
        float ir = iraw[idx];
        float a   = 1.0f / (1.0f + __expf(-fr));
        float inp = (ir / (1.0f + __expf(-ir))) * (1.0f - a);
        h  = fmaf(a, h, inp);
        pa *= a;
        o[idx] = h;
    }
    cA[(size_t)bc * Dd + d] = pa;
    cH[(size_t)bc * Dd + d] = h;
}

__global__ void scan_pass2(const float* __restrict__ cA,
                           const float* __restrict__ cH,
                           float* __restrict__ cIn)
{
    int ch = blockIdx.x * blockDim.x + threadIdx.x;
    int b  = ch / Dd;
    int d  = ch - b * Dd;
    float H = 0.0f;
#pragma unroll
    for (int c = 0; c < NC; c++) {
        size_t idx = ((size_t)b * NC + c) * Dd + d;
        cIn[idx] = H;
        H = fmaf(cA[idx], H, cH[idx]);
    }
}

__global__ void scan_pass3(const float* __restrict__ fraw,
                           const float* __restrict__ cIn,
                           float* __restrict__ o)
{
    const int blocksPerBC = Dd / 256;
    int d  = (blockIdx.x % blocksPerBC) * 256 + threadIdx.x;
    int bc = blockIdx.x / blocksPerBC;
    int b  = bc / NC;
    int c  = bc % NC;
    if (c == 0) return;

    float pa = cIn[(size_t)bc * Dd + d];
    size_t base = ((size_t)b * Tt + (size_t)c * CH) * Dd + d;
#pragma unroll 4
    for (int t = 0; t < CH; t++) {
        size_t idx = base + (size_t)t * Dd;
        float a = 1.0f / (1.0f + __expf(-fraw[idx]));
        pa *= a;
        o[idx] += pa;
    }
}

// ---------------------------------------------------------------------------
// u = tf32_round( RMSNorm(o) * w * (g * sigmoid(g)) ) per (b,t) row
// ---------------------------------------------------------------------------
__global__ __launch_bounds__(256)
void norm_gate_kernel(const float* __restrict__ o,
                      const float* __restrict__ g,
                      const float* __restrict__ w,
                      float* __restrict__ u)
{
    int row = blockIdx.x;
    const float4* op = reinterpret_cast<const float4*>(o + (size_t)row * Dd);
    const float4* gp = reinterpret_cast<const float4*>(g + (size_t)row * Dd);
    const float4* wp = reinterpret_cast<const float4*>(w);
    float4*       up = reinterpret_cast<float4*>(u + (size_t)row * Dd);

    float4 va[2];
    float s = 0.0f;
#pragma unroll
    for (int i = 0; i < 2; i++) {
        va[i] = op[threadIdx.x + i * 256];
        s += va[i].x * va[i].x + va[i].y * va[i].y
           + va[i].z * va[i].z + va[i].w * va[i].w;
    }
#pragma unroll
    for (int k = 16; k > 0; k >>= 1)
        s += __shfl_xor_sync(0xffffffffu, s, k);
    __shared__ float red[8];
    if ((threadIdx.x & 31) == 0) red[threadIdx.x >> 5] = s;
    __syncthreads();
    if (threadIdx.x < 8) {
        float v = red[threadIdx.x];
#pragma unroll
        for (int k = 4; k > 0; k >>= 1)
            v += __shfl_xor_sync(0xffu, v, k);
        if (threadIdx.x == 0) red[0] = v;
    }
    __syncthreads();
    float r = rsqrtf(red[0] * (1.0f / Dd) + EPS);

#pragma unroll
    for (int i = 0; i < 2; i++) {
        float4 vg = gp[threadIdx.x + i * 256];
        float4 vw = wp[threadIdx.x + i * 256];
        float4 out;
        out.x = tf32r(va[i].x * r * vw.x * (vg.x / (1.0f + __expf(-vg.x))));
        out.y = tf32r(va[i].y * r * vw.y * (vg.y / (1.0f + __expf(-vg.y))));
        out.z = tf32r(va[i].z * r * vw.z * (vg.z / (1.0f + __expf(-vg.z))));
        out.w = tf32r(va[i].w * r * vw.w * (vg.w / (1.0f + __expf(-vg.w))));
        up[threadIdx.x + i * 256] = out;
    }
}

// ---------------------------------------------------------------------------
extern "C" void kernel_launch(void* const* d_in, const int* in_sizes, int n_in,
                              void* d_out, int out_size)
{
    const float* x  = (const float*)d_in[0];
    const float* Wi = (const float*)d_in[1];
    const float* Wf = (const float*)d_in[2];
    const float* Wg = (const float*)d_in[3];
    const float* Wo = (const float*)d_in[4];
    const float* gw = (const float*)d_in[5];
    float* out = (float*)d_out;

    float *iraw, *fraw, *gg, *o, *u, *xr, *wr, *cA, *cH, *cIn;
    cudaGetSymbolAddress((void**)&iraw, g_iraw);
    cudaGetSymbolAddress((void**)&fraw, g_fraw);
    cudaGetSymbolAddress((void**)&gg,   g_gg);
    cudaGetSymbolAddress((void**)&o,    g_o);
    cudaGetSymbolAddress((void**)&u,    g_u);
    cudaGetSymbolAddress((void**)&xr,   g_xr);
    cudaGetSymbolAddress((void**)&wr,   g_wr);
    cudaGetSymbolAddress((void**)&cA,   g_cA);
    cudaGetSymbolAddress((void**)&cH,   g_cH);
    cudaGetSymbolAddress((void**)&cIn,  g_cIn);

    cudaFuncSetAttribute(gemm_mma,
                         cudaFuncAttributeMaxDynamicSharedMemorySize, GEMM_SMEM);

    const size_t WSZ = (size_t)Dd * Dd;

    // Pre-round x and weights to tf32 (weights stay in native [K][N] layout)
    {
        int n4x = (int)((size_t)BT * Dd / 4);
        int n4w = (int)(WSZ / 4);
        round_tf32_kernel<<<n4x / 256, 256>>>(x,  xr, n4x);
        round_tf32_kernel<<<n4w / 256, 256>>>(Wi, wr + 0 * WSZ, n4w);
        round_tf32_kernel<<<n4w / 256, 256>>>(Wf, wr + 1 * WSZ, n4w);
        round_tf32_kernel<<<n4w / 256, 256>>>(Wg, wr + 2 * WSZ, n4w);
        round_tf32_kernel<<<n4w / 256, 256>>>(Wo, wr + 3 * WSZ, n4w);
    }

    dim3 ggrid(Dd / BN, BT / BM);   // (16, 128)
    dim3 gblk(256);

    gemm_mma<<<ggrid, gblk, GEMM_SMEM>>>(xr, wr + 0 * WSZ, iraw, BT, Dd, Dd);
    gemm_mma<<<ggrid, gblk, GEMM_SMEM>>>(xr, wr + 1 * WSZ, fraw, BT, Dd, Dd);
    gemm_mma<<<ggrid, gblk, GEMM_SMEM>>>(xr, wr + 2 * WSZ, gg,   BT, Dd, Dd);

    const int scanBlocks = Bb * NC * (Dd / 256);   // 1024
    scan_pass1<<<scanBlocks, 256>>>(iraw, fraw, o, cA, cH);
    scan_pass2<<<(Bb * Dd) / 256, 256>>>(cA, cH, cIn);
    scan_pass3<<<scanBlocks, 256>>>(fraw, cIn, o);

    norm_gate_kernel<<<BT, 256>>>(o, gg, gw, u);

    gemm_mma<<<ggrid, gblk, GEMM_SMEM>>>(u, wr + 3 * WSZ, out, BT, Dd, Dd);
}